// round 7
// baseline (speedup 1.0000x reference)
#include <cuda_runtime.h>
#include <cstdint>

// ---------------------------------------------------------------------------
// CrossAttentionDecoder, tf32 mma.sync, fused K+V projection:
//   q = x@Wq^T ; {k,v} = l@{Wk,Wv}^T in ONE kernel (masked: b uses rows <= b%128)
//   attn per (b,h) (chunked smem, high occupancy) ; out = ao@Wo^T + bo
// ---------------------------------------------------------------------------

#define NHEADS 8
#define DH 64
#define DIM 512
#define NLAT 128
#define NTOK 16
#define NB 1024
#define QROWS (NB * NTOK)      // 16384
#define KVROWS (NB * NLAT)     // 131072

__device__ float g_q [QROWS  * DIM];
__device__ float g_k [KVROWS * DIM];
__device__ float g_v [KVROWS * DIM];
__device__ float g_ao[QROWS  * DIM];

__device__ __forceinline__ uint32_t f2tf32(float x) {
    uint32_t r;
    asm("cvt.rna.tf32.f32 %0, %1;" : "=r"(r) : "f"(x));
    return r;
}

__device__ __forceinline__ void mma_tf32(float* d, const uint32_t* a, const uint32_t* b) {
    asm volatile(
        "mma.sync.aligned.m16n8k8.row.col.f32.tf32.tf32.f32 "
        "{%0,%1,%2,%3}, {%4,%5,%6,%7}, {%8,%9}, {%0,%1,%2,%3};"
        : "+f"(d[0]), "+f"(d[1]), "+f"(d[2]), "+f"(d[3])
        : "r"(a[0]), "r"(a[1]), "r"(a[2]), "r"(a[3]), "r"(b[0]), "r"(b[1]));
}

// Packed smem layout for a 128x16 tf32 tile (64-bit paired fragment LDS):
//   element (x, k): s = k>>3, c = k&3, h = (k>>2)&1
//   word offset = s*1040 + c*260 + x*2 + h
#define TILE_W 2080

__device__ __forceinline__ void stage_ld(const float* __restrict__ src, int tid,
                                         int limit, float4* pv) {
    #pragma unroll
    for (int j = 0; j < 2; j++) {
        const int idx = tid + j * 256;
        const int x   = idx >> 2;
        const int kq  = idx & 3;
        if (x < limit)
            pv[j] = *reinterpret_cast<const float4*>(src + (size_t)x * DIM + kq * 4);
    }
}
__device__ __forceinline__ void stage_st(uint32_t* __restrict__ dst, int tid,
                                         int limit, const float4* pv) {
    #pragma unroll
    for (int j = 0; j < 2; j++) {
        const int idx = tid + j * 256;
        const int x   = idx >> 2;
        const int kq  = idx & 3;
        if (x < limit) {
            uint32_t base = (uint32_t)(kq >> 1) * 1040 + x * 2 + (kq & 1);
            dst[base      ] = f2tf32(pv[j].x);
            dst[base + 260] = f2tf32(pv[j].y);
            dst[base + 520] = f2tf32(pv[j].z);
            dst[base + 780] = f2tf32(pv[j].w);
        }
    }
}

// ---------------------------------------------------------------------------
// Plain tf32 GEMM (q and o projections), unchanged from R6.
// ---------------------------------------------------------------------------
template<bool BIAS>
__global__ __launch_bounds__(256, 2)
void gemm_tf32(const float* __restrict__ A, const float* __restrict__ B,
               const float* __restrict__ bias, float* __restrict__ C)
{
    __shared__ __align__(16) uint32_t Abuf[2][TILE_W];
    __shared__ __align__(16) uint32_t Bbuf[2][TILE_W];

    const int tid  = threadIdx.x;
    const int lane = tid & 31;
    const int warp = tid >> 5;
    const int wm   = warp >> 1;
    const int wn   = warp & 1;
    const size_t m0 = (size_t)blockIdx.y * 128;
    const int    n0 = blockIdx.x * 128;

    const int r = lane >> 2;
    const int c = lane & 3;

    float acc[2][8][4];
    #pragma unroll
    for (int ma = 0; ma < 2; ma++)
        #pragma unroll
        for (int na = 0; na < 8; na++)
            #pragma unroll
            for (int q = 0; q < 4; q++) acc[ma][na][q] = 0.f;

    const float* Ag = A + m0 * DIM;
    const float* Bg = B + (size_t)n0 * DIM;

    float4 pa[2], pb[2];
    stage_ld(Ag, tid, 128, pa);
    stage_ld(Bg, tid, 128, pb);
    stage_st(Abuf[0], tid, 128, pa);
    stage_st(Bbuf[0], tid, 128, pb);
    __syncthreads();

    #pragma unroll 1
    for (int it = 0; it < 32; it++) {
        const int buf = it & 1;
        if (it + 1 < 32) {
            stage_ld(Ag + (it + 1) * 16, tid, 128, pa);
            stage_ld(Bg + (it + 1) * 16, tid, 128, pb);
        }
        #pragma unroll
        for (int s = 0; s < 2; s++) {
            const uint32_t* Ab = &Abuf[buf][s * 1040 + c * 260];
            const uint32_t* Bb = &Bbuf[buf][s * 1040 + c * 260];
            uint32_t af[2][4];
            #pragma unroll
            for (int ma = 0; ma < 2; ma++) {
                const int mb = wm * 32 + ma * 16;
                const uint2 u0 = *reinterpret_cast<const uint2*>(Ab + (mb + r) * 2);
                const uint2 u1 = *reinterpret_cast<const uint2*>(Ab + (mb + r + 8) * 2);
                af[ma][0] = u0.x; af[ma][1] = u1.x; af[ma][2] = u0.y; af[ma][3] = u1.y;
            }
            #pragma unroll
            for (int na = 0; na < 8; na++) {
                const int nb = wn * 64 + na * 8;
                const uint2 bv = *reinterpret_cast<const uint2*>(Bb + (nb + r) * 2);
                uint32_t bf[2] = { bv.x, bv.y };
                mma_tf32(acc[0][na], af[0], bf);
                mma_tf32(acc[1][na], af[1], bf);
            }
        }
        if (it + 1 < 32) {
            stage_st(Abuf[buf ^ 1], tid, 128, pa);
            stage_st(Bbuf[buf ^ 1], tid, 128, pb);
            __syncthreads();
        }
    }

    {
        const int cq = c * 2;
        #pragma unroll
        for (int ma = 0; ma < 2; ma++) {
            const int row0 = wm * 32 + ma * 16 + r;
            const int row1 = row0 + 8;
            #pragma unroll
            for (int na = 0; na < 8; na++) {
                const int col = n0 + wn * 64 + na * 8 + cq;
                float b0 = 0.f, b1 = 0.f;
                if (BIAS) { b0 = bias[col]; b1 = bias[col + 1]; }
                *reinterpret_cast<float2*>(C + (m0 + row0) * DIM + col) =
                    make_float2(acc[ma][na][0] + b0, acc[ma][na][1] + b1);
                *reinterpret_cast<float2*>(C + (m0 + row1) * DIM + col) =
                    make_float2(acc[ma][na][2] + b0, acc[ma][na][3] + b1);
            }
        }
    }
}

// ---------------------------------------------------------------------------
// Fused K+V GEMM: stages A (l) once per k-slab, two B weight matrices, two
// accumulator sets. Masked rows. 256 threads, 1 CTA/SM (128 acc regs).
// ---------------------------------------------------------------------------
__global__ __launch_bounds__(256, 1)
void gemm_kv(const float* __restrict__ A, const float* __restrict__ B0,
             const float* __restrict__ B1, float* __restrict__ C0,
             float* __restrict__ C1)
{
    extern __shared__ __align__(16) uint32_t smkv[];
    uint32_t* Abuf  = smkv;
    uint32_t* B0buf = smkv + 2 * TILE_W;
    uint32_t* B1buf = smkv + 4 * TILE_W;

    const int tid  = threadIdx.x;
    const int lane = tid & 31;
    const int warp = tid >> 5;
    const int wm   = warp >> 1;
    const int wn   = warp & 1;
    const size_t m0 = (size_t)blockIdx.y * 128;
    const int    n0 = blockIdx.x * 128;
    const int limit = (blockIdx.y & 127) + 1;
    const bool active = (wm * 32 < limit);

    const int r = lane >> 2;
    const int c = lane & 3;

    float acc[2][2][8][4];
    #pragma unroll
    for (int o = 0; o < 2; o++)
        #pragma unroll
        for (int ma = 0; ma < 2; ma++)
            #pragma unroll
            for (int na = 0; na < 8; na++)
                #pragma unroll
                for (int q = 0; q < 4; q++) acc[o][ma][na][q] = 0.f;

    const float* Ag  = A  + m0 * DIM;
    const float* B0g = B0 + (size_t)n0 * DIM;
    const float* B1g = B1 + (size_t)n0 * DIM;

    float4 pa[2], pb0[2], pb1[2];
    stage_ld(Ag,  tid, limit, pa);
    stage_ld(B0g, tid, 128,   pb0);
    stage_ld(B1g, tid, 128,   pb1);
    stage_st(Abuf,  tid, limit, pa);
    stage_st(B0buf, tid, 128,   pb0);
    stage_st(B1buf, tid, 128,   pb1);
    __syncthreads();

    #pragma unroll 1
    for (int it = 0; it < 32; it++) {
        const int buf = it & 1;
        if (it + 1 < 32) {
            stage_ld(Ag  + (it + 1) * 16, tid, limit, pa);
            stage_ld(B0g + (it + 1) * 16, tid, 128,   pb0);
            stage_ld(B1g + (it + 1) * 16, tid, 128,   pb1);
        }
        if (active) {
            #pragma unroll
            for (int s = 0; s < 2; s++) {
                const uint32_t* Ab  = &Abuf [buf * TILE_W + s * 1040 + c * 260];
                const uint32_t* Bb0 = &B0buf[buf * TILE_W + s * 1040 + c * 260];
                const uint32_t* Bb1 = &B1buf[buf * TILE_W + s * 1040 + c * 260];
                uint32_t af[2][4];
                #pragma unroll
                for (int ma = 0; ma < 2; ma++) {
                    const int mb = wm * 32 + ma * 16;
                    const uint2 u0 = *reinterpret_cast<const uint2*>(Ab + (mb + r) * 2);
                    const uint2 u1 = *reinterpret_cast<const uint2*>(Ab + (mb + r + 8) * 2);
                    af[ma][0] = u0.x; af[ma][1] = u1.x; af[ma][2] = u0.y; af[ma][3] = u1.y;
                }
                #pragma unroll
                for (int na = 0; na < 8; na++) {
                    const int nb = wn * 64 + na * 8;
                    const uint2 b0 = *reinterpret_cast<const uint2*>(Bb0 + (nb + r) * 2);
                    uint32_t bf0[2] = { b0.x, b0.y };
                    mma_tf32(acc[0][0][na], af[0], bf0);
                    mma_tf32(acc[0][1][na], af[1], bf0);
                    const uint2 b1 = *reinterpret_cast<const uint2*>(Bb1 + (nb + r) * 2);
                    uint32_t bf1[2] = { b1.x, b1.y };
                    mma_tf32(acc[1][0][na], af[0], bf1);
                    mma_tf32(acc[1][1][na], af[1], bf1);
                }
            }
        }
        if (it + 1 < 32) {
            stage_st(Abuf  + (buf ^ 1) * TILE_W, tid, limit, pa);
            stage_st(B0buf + (buf ^ 1) * TILE_W, tid, 128,   pb0);
            stage_st(B1buf + (buf ^ 1) * TILE_W, tid, 128,   pb1);
            __syncthreads();
        }
    }

    if (active) {
        const int cq = c * 2;
        #pragma unroll
        for (int o = 0; o < 2; o++) {
            float* C = (o == 0) ? C0 : C1;
            #pragma unroll
            for (int ma = 0; ma < 2; ma++) {
                const int row0 = wm * 32 + ma * 16 + r;
                const int row1 = row0 + 8;
                #pragma unroll
                for (int na = 0; na < 8; na++) {
                    const int col = n0 + wn * 64 + na * 8 + cq;
                    if (row0 < limit)
                        *reinterpret_cast<float2*>(C + (m0 + row0) * DIM + col) =
                            make_float2(acc[o][ma][na][0], acc[o][ma][na][1]);
                    if (row1 < limit)
                        *reinterpret_cast<float2*>(C + (m0 + row1) * DIM + col) =
                            make_float2(acc[o][ma][na][2], acc[o][ma][na][3]);
                }
            }
        }
    }
}

// ---------------------------------------------------------------------------
// Attention: one block per (b, h), 128 threads. K/V staged in 64-latent
// chunks -> 31 KB smem, reg-capped -> ~6 blocks/SM (was 4).
// ---------------------------------------------------------------------------
#define ACH 64
__global__ __launch_bounds__(128, 6)
void attn_kernel(const float* __restrict__ qb, const float* __restrict__ kb,
                 const float* __restrict__ vb, float* __restrict__ ob)
{
    __shared__ float qs [16 * 68];
    __shared__ float kvs[ACH * 68];
    __shared__ float ss [16 * 132];
    __shared__ float red[16][9];
    __shared__ float rowmax[16], rinv[16];

    const int tid = threadIdx.x;
    const int bh  = blockIdx.x;
    const int b   = bh >> 3;
    const int h   = bh & 7;
    const int L   = (b & 127) + 1;

    const float* qsrc = qb + (size_t)(b * NTOK) * DIM + h * DH;
    const float* ksrc = kb + (size_t)(b * NLAT) * DIM + h * DH;
    const float* vsrc = vb + (size_t)(b * NLAT) * DIM + h * DH;

    // stage q (16 x 64)
    {
        int rr = tid >> 3;
        int cc = (tid & 7) * 8;
        float4 v0 = *reinterpret_cast<const float4*>(qsrc + (size_t)rr * DIM + cc);
        float4 v1 = *reinterpret_cast<const float4*>(qsrc + (size_t)rr * DIM + cc + 4);
        *reinterpret_cast<float4*>(qs + rr * 68 + cc)     = v0;
        *reinterpret_cast<float4*>(qs + rr * 68 + cc + 4) = v1;
    }

    const int i = tid & 15;   // query row
    const int g = tid >> 4;   // 0..7

    // ---- scores in two 64-latent chunks ----
    float mreg = -1e30f;
    #pragma unroll 1
    for (int ch = 0; ch < 2; ch++) {
        const int base = ch * ACH;
        if (base >= L) break;
        if (ch) __syncthreads();                 // kvs reuse
        for (int idx = tid; idx < ACH * 16; idx += 128) {
            int j = base + (idx >> 4), cc = (idx & 15) * 4;
            if (j < L)
                *reinterpret_cast<float4*>(kvs + (idx >> 4) * 68 + cc) =
                    *reinterpret_cast<const float4*>(ksrc + (size_t)j * DIM + cc);
        }
        __syncthreads();

        float sc[8];
        #pragma unroll
        for (int jj = 0; jj < 8; jj++) sc[jj] = 0.f;
        const float* qp = qs + i * 68;
        #pragma unroll 4
        for (int d = 0; d < 64; d += 4) {
            const float4 q4 = *reinterpret_cast<const float4*>(qp + d);
            #pragma unroll
            for (int jj = 0; jj < 8; jj++) {
                const float4 k4 = *reinterpret_cast<const float4*>(kvs + (g * 8 + jj) * 68 + d);
                sc[jj] = fmaf(q4.x, k4.x, fmaf(q4.y, k4.y, fmaf(q4.z, k4.z, fmaf(q4.w, k4.w, sc[jj]))));
            }
        }
        #pragma unroll
        for (int jj = 0; jj < 8; jj++) {
            int j = base + g * 8 + jj;
            if (j < L) {
                float s = sc[jj] * 0.125f;
                ss[i * 132 + j] = s;
                mreg = fmaxf(mreg, s);
            }
        }
    }
    red[i][g] = mreg;
    __syncthreads();

    if (tid < 16) {
        float m = red[tid][0];
        #pragma unroll
        for (int t = 1; t < 8; t++) m = fmaxf(m, red[tid][t]);
        rowmax[tid] = m;
    }
    __syncthreads();

    // exp + partial sum (thread covers j = g*16 .. g*16+15)
    {
        const float m = rowmax[i];
        float s = 0.f;
        #pragma unroll
        for (int jj = 0; jj < 16; jj++) {
            int j = g * 16 + jj;
            if (j < L) {
                float e = __expf(ss[i * 132 + j] - m);
                ss[i * 132 + j] = e;
                s += e;
            }
        }
        red[i][g] = s;
    }
    __syncthreads();
    if (tid < 16) {
        float s = red[tid][0];
        #pragma unroll
        for (int t = 1; t < 8; t++) s += red[tid][t];
        rinv[tid] = 1.f / s;
    }
    __syncthreads();

    // ---- PV in two chunks ----
    float acc[8];
    #pragma unroll
    for (int rr = 0; rr < 8; rr++) acc[rr] = 0.f;
    #pragma unroll 1
    for (int ch = 0; ch < 2; ch++) {
        const int base = ch * ACH;
        if (base >= L) break;
        __syncthreads();                         // kvs reuse
        for (int idx = tid; idx < ACH * 16; idx += 128) {
            int j = base + (idx >> 4), cc = (idx & 15) * 4;
            if (j < L)
                *reinterpret_cast<float4*>(kvs + (idx >> 4) * 68 + cc) =
                    *reinterpret_cast<const float4*>(vsrc + (size_t)j * DIM + cc);
        }
        __syncthreads();
        const int jend = (L < base + ACH ? L : base + ACH);
        for (int j = base; j < jend; j++) {
            const float p = ss[i * 132 + j];
            const float4 v0 = *reinterpret_cast<const float4*>(kvs + (j - base) * 68 + g * 8);
            const float4 v1 = *reinterpret_cast<const float4*>(kvs + (j - base) * 68 + g * 8 + 4);
            acc[0] = fmaf(p, v0.x, acc[0]); acc[1] = fmaf(p, v0.y, acc[1]);
            acc[2] = fmaf(p, v0.z, acc[2]); acc[3] = fmaf(p, v0.w, acc[3]);
            acc[4] = fmaf(p, v1.x, acc[4]); acc[5] = fmaf(p, v1.y, acc[5]);
            acc[6] = fmaf(p, v1.z, acc[6]); acc[7] = fmaf(p, v1.w, acc[7]);
        }
    }
    const float inv = rinv[i];
    float* dst = ob + (size_t)(b * NTOK + i) * DIM + h * DH + g * 8;
    *reinterpret_cast<float4*>(dst) =
        make_float4(acc[0] * inv, acc[1] * inv, acc[2] * inv, acc[3] * inv);
    *reinterpret_cast<float4*>(dst + 4) =
        make_float4(acc[4] * inv, acc[5] * inv, acc[6] * inv, acc[7] * inv);
}

// ---------------------------------------------------------------------------
extern "C" void kernel_launch(void* const* d_in, const int* in_sizes, int n_in,
                              void* d_out, int out_size)
{
    const float* x  = (const float*)d_in[0];
    const float* l  = (const float*)d_in[1];
    const float* Wq = (const float*)d_in[2];
    const float* Wk = (const float*)d_in[3];
    const float* Wv = (const float*)d_in[4];
    const float* Wo = (const float*)d_in[5];
    const float* bo = (const float*)d_in[6];
    float* out = (float*)d_out;

    void *pq, *pk, *pv, *pa;
    cudaGetSymbolAddress(&pq, g_q);
    cudaGetSymbolAddress(&pk, g_k);
    cudaGetSymbolAddress(&pv, g_v);
    cudaGetSymbolAddress(&pa, g_ao);
    float* q  = (float*)pq;
    float* k  = (float*)pk;
    float* v  = (float*)pv;
    float* ao = (float*)pa;

    const int KV_SMEM = 6 * TILE_W * 4;   // 49920 B
    cudaFuncSetAttribute(gemm_kv, cudaFuncAttributeMaxDynamicSharedMemorySize, KV_SMEM);

    dim3 blk(256);
    gemm_tf32<false><<<dim3(4, QROWS / 128), blk>>>(x, Wq, nullptr, q);
    gemm_kv<<<dim3(4, NB), blk, KV_SMEM>>>(l, Wk, Wv, k, v);
    attn_kernel<<<NB * NHEADS, 128>>>(q, k, v, ao);
    gemm_tf32<true><<<dim3(4, QROWS / 128), blk>>>(ao, Wo, bo, out);
}

// round 10
// speedup vs baseline: 2.1753x; 2.1753x over previous
#include <cuda_runtime.h>
#include <cuda_fp16.h>
#include <cstdint>

// ---------------------------------------------------------------------------
// CrossAttentionDecoder, fp16 mma.sync (m16n8k16) GEMMs, split k/v kernels:
//   q = x@Wq^T ; k = l@Wk^T ; v = l@Wv^T (masked: batch b uses rows <= b%128)
//   attn per (b,h) (chunked smem, high occupancy) ; out = ao@Wo^T + bo
// fp16 rne has the same 10-bit mantissa as tf32 -> same accuracy, 2x K/instr.
// ---------------------------------------------------------------------------

#define NHEADS 8
#define DH 64
#define DIM 512
#define NLAT 128
#define NTOK 16
#define NB 1024
#define QROWS (NB * NTOK)      // 16384
#define KVROWS (NB * NLAT)     // 131072

__device__ float g_q [QROWS  * DIM];
__device__ float g_k [KVROWS * DIM];
__device__ float g_v [KVROWS * DIM];
__device__ float g_ao[QROWS  * DIM];

__device__ __forceinline__ uint32_t packh2(float lo, float hi) {
    __half2 h = __floats2half2_rn(lo, hi);   // .x = lo = low 16 bits (even k)
    return *reinterpret_cast<uint32_t*>(&h);
}

__device__ __forceinline__ void mma_f16(float* d, const uint32_t* a, const uint32_t* b) {
    asm volatile(
        "mma.sync.aligned.m16n8k16.row.col.f32.f16.f16.f32 "
        "{%0,%1,%2,%3}, {%4,%5,%6,%7}, {%8,%9}, {%0,%1,%2,%3};"
        : "+f"(d[0]), "+f"(d[1]), "+f"(d[2]), "+f"(d[3])
        : "r"(a[0]), "r"(a[1]), "r"(a[2]), "r"(a[3]), "r"(b[0]), "r"(b[1]));
}

// ---------------------------------------------------------------------------
// Packed fp16x2 smem layout, per 128x16 (k16) tile:
//   word(x, kp): c = kp&3 (plane), h = kp>>2  ->  c*264 + x*2 + h
//   PLANE=264 -> fragment LDS.64 conflict-free (4c+r distinct per 16-lane phase)
//   TILE16 = 4*264 = 1056 words. Stage (BK=32) = 2 tiles = 2112 words.
// Fragment at (row x, lane c): LDS.64 -> {kp c, kp c+4} = {a0,a2} / {b0,b1}.
// ---------------------------------------------------------------------------
#define TILE16 1056
#define STAGE_W (2 * TILE16)

// load 16 floats: row x = tid>>1, k-half kh = tid&1, both k16 tiles of the slab
__device__ __forceinline__ void stage_ld(const float* __restrict__ src, int tid,
                                         int limit, float4* pv) {
    const int x  = tid >> 1;
    const int kh = tid & 1;
    if (x < limit) {
        #pragma unroll
        for (int t = 0; t < 2; t++) {
            const float* p = src + (size_t)x * DIM + t * 16 + kh * 8;
            pv[t * 2 + 0] = *reinterpret_cast<const float4*>(p);
            pv[t * 2 + 1] = *reinterpret_cast<const float4*>(p + 4);
        }
    }
}
// store as fp16x2: thread's 8 floats per tile -> planes e=0..3 at h=kh.
// STS banks = (8e + 2x + kh) mod 32: all 32 lanes distinct -> conflict-free.
__device__ __forceinline__ void stage_st(uint32_t* __restrict__ dst, int tid,
                                         int limit, const float4* pv) {
    const int x  = tid >> 1;
    const int kh = tid & 1;
    if (x < limit) {
        #pragma unroll
        for (int t = 0; t < 2; t++) {
            const float4 lo = pv[t * 2 + 0], hi = pv[t * 2 + 1];
            uint32_t* base = dst + t * TILE16 + x * 2 + kh;
            base[0 * 264] = packh2(lo.x, lo.y);
            base[1 * 264] = packh2(lo.z, lo.w);
            base[2 * 264] = packh2(hi.x, hi.y);
            base[3 * 264] = packh2(hi.z, hi.w);
        }
    }
}

// ---------------------------------------------------------------------------
// fp16 GEMM  C[M,N] = A[M,K] @ B[N,K]^T (+bias), K = N = 512.
// Block 128x128, BK=32 double-buffered, 256 threads = 8 warps (4M x 2N).
// MASKED: only rows < (blockIdx.y & 127)+1 are live (warp-granularity skip).
// ---------------------------------------------------------------------------
template<bool MASKED, bool BIAS>
__global__ __launch_bounds__(256, 2)
void gemm_f16(const float* __restrict__ A, const float* __restrict__ B,
              const float* __restrict__ bias, float* __restrict__ C)
{
    __shared__ __align__(16) uint32_t Abuf[2][STAGE_W];
    __shared__ __align__(16) uint32_t Bbuf[2][STAGE_W];

    const int tid  = threadIdx.x;
    const int lane = tid & 31;
    const int warp = tid >> 5;
    const int wm   = warp >> 1;   // 0..3  M tile of 32
    const int wn   = warp & 1;    // 0..1  N tile of 64
    const size_t m0 = (size_t)blockIdx.y * 128;
    const int    n0 = blockIdx.x * 128;
    const int limit = MASKED ? ((blockIdx.y & 127) + 1) : 128;
    const bool active = (!MASKED) || (wm * 32 < limit);

    const int r = lane >> 2;      // 0..7
    const int c = lane & 3;       // 0..3

    float acc[2][8][4];
    #pragma unroll
    for (int ma = 0; ma < 2; ma++)
        #pragma unroll
        for (int na = 0; na < 8; na++)
            #pragma unroll
            for (int q = 0; q < 4; q++) acc[ma][na][q] = 0.f;

    const float* Ag = A + m0 * DIM;
    const float* Bg = B + (size_t)n0 * DIM;

    float4 pa[4], pb[4];
    stage_ld(Ag, tid, limit, pa);
    stage_ld(Bg, tid, 128,   pb);
    stage_st(Abuf[0], tid, limit, pa);
    stage_st(Bbuf[0], tid, 128,   pb);
    __syncthreads();

    #pragma unroll 1
    for (int it = 0; it < 16; it++) {       // 16 stages x BK=32
        const int buf = it & 1;
        if (it + 1 < 16) {
            stage_ld(Ag + (it + 1) * 32, tid, limit, pa);
            stage_ld(Bg + (it + 1) * 32, tid, 128,   pb);
        }
        if (active) {
            #pragma unroll
            for (int t = 0; t < 2; t++) {    // two k16 tiles
                const uint32_t* Ab = &Abuf[buf][t * TILE16 + c * 264];
                const uint32_t* Bb = &Bbuf[buf][t * TILE16 + c * 264];
                uint32_t af[2][4];
                #pragma unroll
                for (int ma = 0; ma < 2; ma++) {
                    const int mb = wm * 32 + ma * 16;
                    const uint2 u0 = *reinterpret_cast<const uint2*>(Ab + (mb + r) * 2);
                    const uint2 u1 = *reinterpret_cast<const uint2*>(Ab + (mb + r + 8) * 2);
                    af[ma][0] = u0.x; af[ma][1] = u1.x; af[ma][2] = u0.y; af[ma][3] = u1.y;
                }
                #pragma unroll
                for (int na = 0; na < 8; na++) {
                    const int nb = wn * 64 + na * 8;
                    const uint2 bv = *reinterpret_cast<const uint2*>(Bb + (nb + r) * 2);
                    uint32_t bf[2] = { bv.x, bv.y };
                    mma_f16(acc[0][na], af[0], bf);
                    mma_f16(acc[1][na], af[1], bf);
                }
            }
        }
        if (it + 1 < 16) {
            stage_st(Abuf[buf ^ 1], tid, limit, pa);
            stage_st(Bbuf[buf ^ 1], tid, 128,   pb);
            __syncthreads();
        }
    }

    // ---- epilogue (same D layout as m16n8 tf32) ----
    if (active) {
        const int cq = c * 2;
        #pragma unroll
        for (int ma = 0; ma < 2; ma++) {
            const int row0 = wm * 32 + ma * 16 + r;
            const int row1 = row0 + 8;
            #pragma unroll
            for (int na = 0; na < 8; na++) {
                const int col = n0 + wn * 64 + na * 8 + cq;
                float b0 = 0.f, b1 = 0.f;
                if (BIAS) { b0 = bias[col]; b1 = bias[col + 1]; }
                if ((!MASKED) || (row0 < limit))
                    *reinterpret_cast<float2*>(C + (m0 + row0) * DIM + col) =
                        make_float2(acc[ma][na][0] + b0, acc[ma][na][1] + b1);
                if ((!MASKED) || (row1 < limit))
                    *reinterpret_cast<float2*>(C + (m0 + row1) * DIM + col) =
                        make_float2(acc[ma][na][2] + b0, acc[ma][na][3] + b1);
            }
        }
    }
}

// ---------------------------------------------------------------------------
// Attention: one block per (b, h), 128 threads. K/V staged in 64-latent
// chunks -> ~31 KB smem, reg-capped -> ~6 blocks/SM.
// ---------------------------------------------------------------------------
#define ACH 64
__global__ __launch_bounds__(128, 6)
void attn_kernel(const float* __restrict__ qb, const float* __restrict__ kb,
                 const float* __restrict__ vb, float* __restrict__ ob)
{
    __shared__ float qs [16 * 68];
    __shared__ float kvs[ACH * 68];
    __shared__ float ss [16 * 132];
    __shared__ float red[16][9];
    __shared__ float rowmax[16], rinv[16];

    const int tid = threadIdx.x;
    const int bh  = blockIdx.x;
    const int b   = bh >> 3;
    const int h   = bh & 7;
    const int L   = (b & 127) + 1;

    const float* qsrc = qb + (size_t)(b * NTOK) * DIM + h * DH;
    const float* ksrc = kb + (size_t)(b * NLAT) * DIM + h * DH;
    const float* vsrc = vb + (size_t)(b * NLAT) * DIM + h * DH;

    {
        int rr = tid >> 3;
        int cc = (tid & 7) * 8;
        float4 v0 = *reinterpret_cast<const float4*>(qsrc + (size_t)rr * DIM + cc);
        float4 v1 = *reinterpret_cast<const float4*>(qsrc + (size_t)rr * DIM + cc + 4);
        *reinterpret_cast<float4*>(qs + rr * 68 + cc)     = v0;
        *reinterpret_cast<float4*>(qs + rr * 68 + cc + 4) = v1;
    }

    const int i = tid & 15;
    const int g = tid >> 4;

    float mreg = -1e30f;
    #pragma unroll 1
    for (int ch = 0; ch < 2; ch++) {
        const int base = ch * ACH;
        if (base >= L) break;
        if (ch) __syncthreads();
        for (int idx = tid; idx < ACH * 16; idx += 128) {
            int j = base + (idx >> 4), cc = (idx & 15) * 4;
            if (j < L)
                *reinterpret_cast<float4*>(kvs + (idx >> 4) * 68 + cc) =
                    *reinterpret_cast<const float4*>(ksrc + (size_t)j * DIM + cc);
        }
        __syncthreads();

        float sc[8];
        #pragma unroll
        for (int jj = 0; jj < 8; jj++) sc[jj] = 0.f;
        const float* qp = qs + i * 68;
        #pragma unroll 4
        for (int d = 0; d < 64; d += 4) {
            const float4 q4 = *reinterpret_cast<const float4*>(qp + d);
            #pragma unroll
            for (int jj = 0; jj < 8; jj++) {
                const float4 k4 = *reinterpret_cast<const float4*>(kvs + (g * 8 + jj) * 68 + d);
                sc[jj] = fmaf(q4.x, k4.x, fmaf(q4.y, k4.y, fmaf(q4.z, k4.z, fmaf(q4.w, k4.w, sc[jj]))));
            }
        }
        #pragma unroll
        for (int jj = 0; jj < 8; jj++) {
            int j = base + g * 8 + jj;
            if (j < L) {
                float s = sc[jj] * 0.125f;
                ss[i * 132 + j] = s;
                mreg = fmaxf(mreg, s);
            }
        }
    }
    red[i][g] = mreg;
    __syncthreads();

    if (tid < 16) {
        float m = red[tid][0];
        #pragma unroll
        for (int t = 1; t < 8; t++) m = fmaxf(m, red[tid][t]);
        rowmax[tid] = m;
    }
    __syncthreads();

    {
        const float m = rowmax[i];
        float s = 0.f;
        #pragma unroll
        for (int jj = 0; jj < 16; jj++) {
            int j = g * 16 + jj;
            if (j < L) {
                float e = __expf(ss[i * 132 + j] - m);
                ss[i * 132 + j] = e;
                s += e;
            }
        }
        red[i][g] = s;
    }
    __syncthreads();
    if (tid < 16) {
        float s = red[tid][0];
        #pragma unroll
        for (int t = 1; t < 8; t++) s += red[tid][t];
        rinv[tid] = 1.f / s;
    }
    __syncthreads();

    float acc[8];
    #pragma unroll
    for (int rr = 0; rr < 8; rr++) acc[rr] = 0.f;
    #pragma unroll 1
    for (int ch = 0; ch < 2; ch++) {
        const int base = ch * ACH;
        if (base >= L) break;
        __syncthreads();
        for (int idx = tid; idx < ACH * 16; idx += 128) {
            int j = base + (idx >> 4), cc = (idx & 15) * 4;
            if (j < L)
                *reinterpret_cast<float4*>(kvs + (idx >> 4) * 68 + cc) =
                    *reinterpret_cast<const float4*>(vsrc + (size_t)j * DIM + cc);
        }
        __syncthreads();
        const int jend = (L < base + ACH ? L : base + ACH);
        for (int j = base; j < jend; j++) {
            const float p = ss[i * 132 + j];
            const float4 v0 = *reinterpret_cast<const float4*>(kvs + (j - base) * 68 + g * 8);
            const float4 v1 = *reinterpret_cast<const float4*>(kvs + (j - base) * 68 + g * 8 + 4);
            acc[0] = fmaf(p, v0.x, acc[0]); acc[1] = fmaf(p, v0.y, acc[1]);
            acc[2] = fmaf(p, v0.z, acc[2]); acc[3] = fmaf(p, v0.w, acc[3]);
            acc[4] = fmaf(p, v1.x, acc[4]); acc[5] = fmaf(p, v1.y, acc[5]);
            acc[6] = fmaf(p, v1.z, acc[6]); acc[7] = fmaf(p, v1.w, acc[7]);
        }
    }
    const float inv = rinv[i];
    float* dst = ob + (size_t)(b * NTOK + i) * DIM + h * DH + g * 8;
    *reinterpret_cast<float4*>(dst) =
        make_float4(acc[0] * inv, acc[1] * inv, acc[2] * inv, acc[3] * inv);
    *reinterpret_cast<float4*>(dst + 4) =
        make_float4(acc[4] * inv, acc[5] * inv, acc[6] * inv, acc[7] * inv);
}

// ---------------------------------------------------------------------------
extern "C" void kernel_launch(void* const* d_in, const int* in_sizes, int n_in,
                              void* d_out, int out_size)
{
    const float* x  = (const float*)d_in[0];
    const float* l  = (const float*)d_in[1];
    const float* Wq = (const float*)d_in[2];
    const float* Wk = (const float*)d_in[3];
    const float* Wv = (const float*)d_in[4];
    const float* Wo = (const float*)d_in[5];
    const float* bo = (const float*)d_in[6];
    float* out = (float*)d_out;

    void *pq, *pk, *pv, *pa;
    cudaGetSymbolAddress(&pq, g_q);
    cudaGetSymbolAddress(&pk, g_k);
    cudaGetSymbolAddress(&pv, g_v);
    cudaGetSymbolAddress(&pa, g_ao);
    float* q  = (float*)pq;
    float* k  = (float*)pk;
    float* v  = (float*)pv;
    float* ao = (float*)pa;

    dim3 blk(256);
    gemm_f16<false, false><<<dim3(4, QROWS / 128), blk>>>(x, Wq, nullptr, q);
    gemm_f16<true,  false><<<dim3(4, NB), blk>>>(l, Wk, nullptr, k);
    gemm_f16<true,  false><<<dim3(4, NB), blk>>>(l, Wv, nullptr, v);
    attn_kernel<<<NB * NHEADS, 128>>>(q, k, v, ao);
    gemm_f16<false, true><<<dim3(4, QROWS / 128), blk>>>(ao, Wo, bo, out);
}

// round 11
// speedup vs baseline: 2.8142x; 1.2937x over previous
#include <cuda_runtime.h>
#include <cuda_fp16.h>
#include <cstdint>

// ---------------------------------------------------------------------------
// CrossAttentionDecoder, fp16 mma.sync GEMMs; k/v projections run on a
// DENSELY PACKED set of live latent rows (batch b owns rows j <= b%128):
//   live rows total 66048 = 516 CTA row-tiles of 128, zero masked work.
// ---------------------------------------------------------------------------

#define NHEADS 8
#define DH 64
#define DIM 512
#define NLAT 128
#define NTOK 16
#define NB 1024
#define QROWS (NB * NTOK)      // 16384
#define KVROWS (NB * NLAT)     // 131072
#define LIVE_PER_PERIOD 8256   // sum_{m=0}^{127} (m+1)
#define PACKED_TILES 516       // 8 periods * 8256 / 128

__device__ float g_q [QROWS  * DIM];
__device__ float g_k [KVROWS * DIM];
__device__ float g_v [KVROWS * DIM];
__device__ float g_ao[QROWS  * DIM];

__device__ __forceinline__ uint32_t packh2(float lo, float hi) {
    __half2 h = __floats2half2_rn(lo, hi);
    return *reinterpret_cast<uint32_t*>(&h);
}

__device__ __forceinline__ void mma_f16(float* d, const uint32_t* a, const uint32_t* b) {
    asm volatile(
        "mma.sync.aligned.m16n8k16.row.col.f32.f16.f16.f32 "
        "{%0,%1,%2,%3}, {%4,%5,%6,%7}, {%8,%9}, {%0,%1,%2,%3};"
        : "+f"(d[0]), "+f"(d[1]), "+f"(d[2]), "+f"(d[3])
        : "r"(a[0]), "r"(a[1]), "r"(a[2]), "r"(a[3]), "r"(b[0]), "r"(b[1]));
}

// live-row index t -> global latent row (b*128 + j)
__device__ __forceinline__ int map_row(int t) {
    const int P  = t / LIVE_PER_PERIOD;
    const int tp = t - P * LIVE_PER_PERIOD;
    int m = (int)((sqrtf((float)(8 * tp + 1)) - 1.0f) * 0.5f);
    while ((m + 1) * (m + 2) / 2 <= tp) m++;     // integer safety
    while (m * (m + 1) / 2 > tp) m--;
    const int j = tp - m * (m + 1) / 2;
    return ((P << 7) + m) * 128 + j;             // b = P*128 + m
}

// ---------------------------------------------------------------------------
// Packed fp16x2 smem layout per 128x16 (k16) tile:
//   word(x, kp): plane c = kp&3, h = kp>>2  ->  c*264 + x*2 + h
#define TILE16 1056
#define STAGE_W (2 * TILE16)

__device__ __forceinline__ void stage_ld_row(const float* __restrict__ rowp, int kh,
                                             float4* pv) {
    #pragma unroll
    for (int t = 0; t < 2; t++) {
        const float* p = rowp + t * 16 + kh * 8;
        pv[t * 2 + 0] = *reinterpret_cast<const float4*>(p);
        pv[t * 2 + 1] = *reinterpret_cast<const float4*>(p + 4);
    }
}
__device__ __forceinline__ void stage_st(uint32_t* __restrict__ dst, int x, int kh,
                                         const float4* pv) {
    #pragma unroll
    for (int t = 0; t < 2; t++) {
        const float4 lo = pv[t * 2 + 0], hi = pv[t * 2 + 1];
        uint32_t* base = dst + t * TILE16 + x * 2 + kh;
        base[0 * 264] = packh2(lo.x, lo.y);
        base[1 * 264] = packh2(lo.z, lo.w);
        base[2 * 264] = packh2(hi.x, hi.y);
        base[3 * 264] = packh2(hi.z, hi.w);
    }
}

// ---------------------------------------------------------------------------
// Core mainloop shared by both GEMM variants. A row source is an arbitrary
// per-thread pointer (identity or packed-map); epilogue rows likewise.
// Block 128x128, BK=32 double-buffered, 256 threads = 8 warps (4M x 2N).
// ---------------------------------------------------------------------------
template<bool BIAS>
__device__ __forceinline__ void gemm_body(
    const float* __restrict__ Arow,    // this thread's staging row base (+kt)
    const float* __restrict__ Bg,      // B block base
    const float* __restrict__ bias,
    float* __restrict__ C,
    const size_t* __restrict__ crow,   // 4 epilogue output row offsets (els)
    int n0)
{
    __shared__ __align__(16) uint32_t Abuf[2][STAGE_W];
    __shared__ __align__(16) uint32_t Bbuf[2][STAGE_W];

    const int tid  = threadIdx.x;
    const int lane = tid & 31;
    const int warp = tid >> 5;
    const int wm   = warp >> 1;
    const int wn   = warp & 1;
    const int x    = tid >> 1;
    const int kh   = tid & 1;
    const int r    = lane >> 2;
    const int c    = lane & 3;

    const float* Brow = Bg + (size_t)x * DIM + 0;

    float acc[2][8][4];
    #pragma unroll
    for (int ma = 0; ma < 2; ma++)
        #pragma unroll
        for (int na = 0; na < 8; na++)
            #pragma unroll
            for (int q = 0; q < 4; q++) acc[ma][na][q] = 0.f;

    float4 pa[4], pb[4];
    stage_ld_row(Arow, kh, pa);
    stage_ld_row(Brow, kh, pb);
    stage_st(Abuf[0], x, kh, pa);
    stage_st(Bbuf[0], x, kh, pb);
    __syncthreads();

    #pragma unroll 1
    for (int it = 0; it < 16; it++) {
        const int buf = it & 1;
        if (it + 1 < 16) {
            stage_ld_row(Arow + (it + 1) * 32, kh, pa);
            stage_ld_row(Brow + (it + 1) * 32, kh, pb);
        }
        #pragma unroll
        for (int t = 0; t < 2; t++) {
            const uint32_t* Ab = &Abuf[buf][t * TILE16 + c * 264];
            const uint32_t* Bb = &Bbuf[buf][t * TILE16 + c * 264];
            uint32_t af[2][4];
            #pragma unroll
            for (int ma = 0; ma < 2; ma++) {
                const int mb = wm * 32 + ma * 16;
                const uint2 u0 = *reinterpret_cast<const uint2*>(Ab + (mb + r) * 2);
                const uint2 u1 = *reinterpret_cast<const uint2*>(Ab + (mb + r + 8) * 2);
                af[ma][0] = u0.x; af[ma][1] = u1.x; af[ma][2] = u0.y; af[ma][3] = u1.y;
            }
            #pragma unroll
            for (int na = 0; na < 8; na++) {
                const int nb = wn * 64 + na * 8;
                const uint2 bv = *reinterpret_cast<const uint2*>(Bb + (nb + r) * 2);
                uint32_t bf[2] = { bv.x, bv.y };
                mma_f16(acc[0][na], af[0], bf);
                mma_f16(acc[1][na], af[1], bf);
            }
        }
        if (it + 1 < 16) {
            stage_st(Abuf[buf ^ 1], x, kh, pa);
            stage_st(Bbuf[buf ^ 1], x, kh, pb);
            __syncthreads();
        }
    }

    const int cq = c * 2;
    #pragma unroll
    for (int ma = 0; ma < 2; ma++) {
        #pragma unroll
        for (int half = 0; half < 2; half++) {
            float* crowp = C + crow[ma * 2 + half] + n0 + wn * 64 + cq;
            const int a0 = half * 2;
            #pragma unroll
            for (int na = 0; na < 8; na++) {
                const int col = n0 + wn * 64 + na * 8 + cq;
                float b0 = 0.f, b1 = 0.f;
                if (BIAS) { b0 = bias[col]; b1 = bias[col + 1]; }
                *reinterpret_cast<float2*>(crowp + na * 8) =
                    make_float2(acc[ma][na][a0] + b0, acc[ma][na][a0 + 1] + b1);
            }
        }
    }
}

// Plain GEMM (q / o projections): identity row mapping.
template<bool BIAS>
__global__ __launch_bounds__(256, 2)
void gemm_f16(const float* __restrict__ A, const float* __restrict__ B,
              const float* __restrict__ bias, float* __restrict__ C)
{
    const size_t m0 = (size_t)blockIdx.y * 128;
    const int    n0 = blockIdx.x * 128;
    const int tid = threadIdx.x, lane = tid & 31, warp = tid >> 5;
    const int wm = warp >> 1, r = lane >> 2;

    const float* Arow = A + (m0 + (tid >> 1)) * DIM;
    size_t crow[4];
    #pragma unroll
    for (int ma = 0; ma < 2; ma++) {
        crow[ma * 2 + 0] = (m0 + wm * 32 + ma * 16 + r) * DIM;
        crow[ma * 2 + 1] = (m0 + wm * 32 + ma * 16 + r + 8) * DIM;
    }
    gemm_body<BIAS>(Arow, B + (size_t)n0 * DIM, bias, C, crow, n0);
}

// Packed GEMM (k / v projections): row-tile of 128 consecutive LIVE rows.
__global__ __launch_bounds__(256, 2)
void gemm_f16_packed(const float* __restrict__ A, const float* __restrict__ B,
                     float* __restrict__ C)
{
    const int t0 = blockIdx.y * 128;
    const int n0 = blockIdx.x * 128;
    const int tid = threadIdx.x, lane = tid & 31, warp = tid >> 5;
    const int wm = warp >> 1, r = lane >> 2;

    const float* Arow = A + (size_t)map_row(t0 + (tid >> 1)) * DIM;
    size_t crow[4];
    #pragma unroll
    for (int ma = 0; ma < 2; ma++) {
        crow[ma * 2 + 0] = (size_t)map_row(t0 + wm * 32 + ma * 16 + r) * DIM;
        crow[ma * 2 + 1] = (size_t)map_row(t0 + wm * 32 + ma * 16 + r + 8) * DIM;
    }
    gemm_body<false>(Arow, B + (size_t)n0 * DIM, nullptr, C, crow, n0);
}

// ---------------------------------------------------------------------------
// Attention: one block per (b, h), 128 threads, 64-latent chunked smem.
// ---------------------------------------------------------------------------
#define ACH 64
__global__ __launch_bounds__(128, 6)
void attn_kernel(const float* __restrict__ qb, const float* __restrict__ kb,
                 const float* __restrict__ vb, float* __restrict__ ob)
{
    __shared__ float qs [16 * 68];
    __shared__ float kvs[ACH * 68];
    __shared__ float ss [16 * 132];
    __shared__ float red[16][9];
    __shared__ float rowmax[16], rinv[16];

    const int tid = threadIdx.x;
    const int bh  = blockIdx.x;
    const int b   = bh >> 3;
    const int h   = bh & 7;
    const int L   = (b & 127) + 1;

    const float* qsrc = qb + (size_t)(b * NTOK) * DIM + h * DH;
    const float* ksrc = kb + (size_t)(b * NLAT) * DIM + h * DH;
    const float* vsrc = vb + (size_t)(b * NLAT) * DIM + h * DH;

    {
        int rr = tid >> 3;
        int cc = (tid & 7) * 8;
        float4 v0 = *reinterpret_cast<const float4*>(qsrc + (size_t)rr * DIM + cc);
        float4 v1 = *reinterpret_cast<const float4*>(qsrc + (size_t)rr * DIM + cc + 4);
        *reinterpret_cast<float4*>(qs + rr * 68 + cc)     = v0;
        *reinterpret_cast<float4*>(qs + rr * 68 + cc + 4) = v1;
    }

    const int i = tid & 15;
    const int g = tid >> 4;

    float mreg = -1e30f;
    #pragma unroll 1
    for (int ch = 0; ch < 2; ch++) {
        const int base = ch * ACH;
        if (base >= L) break;
        if (ch) __syncthreads();
        for (int idx = tid; idx < ACH * 16; idx += 128) {
            int j = base + (idx >> 4), cc = (idx & 15) * 4;
            if (j < L)
                *reinterpret_cast<float4*>(kvs + (idx >> 4) * 68 + cc) =
                    *reinterpret_cast<const float4*>(ksrc + (size_t)j * DIM + cc);
        }
        __syncthreads();

        float sc[8];
        #pragma unroll
        for (int jj = 0; jj < 8; jj++) sc[jj] = 0.f;
        const float* qp = qs + i * 68;
        #pragma unroll 4
        for (int d = 0; d < 64; d += 4) {
            const float4 q4 = *reinterpret_cast<const float4*>(qp + d);
            #pragma unroll
            for (int jj = 0; jj < 8; jj++) {
                const float4 k4 = *reinterpret_cast<const float4*>(kvs + (g * 8 + jj) * 68 + d);
                sc[jj] = fmaf(q4.x, k4.x, fmaf(q4.y, k4.y, fmaf(q4.z, k4.z, fmaf(q4.w, k4.w, sc[jj]))));
            }
        }
        #pragma unroll
        for (int jj = 0; jj < 8; jj++) {
            int j = base + g * 8 + jj;
            if (j < L) {
                float s = sc[jj] * 0.125f;
                ss[i * 132 + j] = s;
                mreg = fmaxf(mreg, s);
            }
        }
    }
    red[i][g] = mreg;
    __syncthreads();

    if (tid < 16) {
        float m = red[tid][0];
        #pragma unroll
        for (int t = 1; t < 8; t++) m = fmaxf(m, red[tid][t]);
        rowmax[tid] = m;
    }
    __syncthreads();

    {
        const float m = rowmax[i];
        float s = 0.f;
        #pragma unroll
        for (int jj = 0; jj < 16; jj++) {
            int j = g * 16 + jj;
            if (j < L) {
                float e = __expf(ss[i * 132 + j] - m);
                ss[i * 132 + j] = e;
                s += e;
            }
        }
        red[i][g] = s;
    }
    __syncthreads();
    if (tid < 16) {
        float s = red[tid][0];
        #pragma unroll
        for (int t = 1; t < 8; t++) s += red[tid][t];
        rinv[tid] = 1.f / s;
    }
    __syncthreads();

    float acc[8];
    #pragma unroll
    for (int rr = 0; rr < 8; rr++) acc[rr] = 0.f;
    #pragma unroll 1
    for (int ch = 0; ch < 2; ch++) {
        const int base = ch * ACH;
        if (base >= L) break;
        __syncthreads();
        for (int idx = tid; idx < ACH * 16; idx += 128) {
            int j = base + (idx >> 4), cc = (idx & 15) * 4;
            if (j < L)
                *reinterpret_cast<float4*>(kvs + (idx >> 4) * 68 + cc) =
                    *reinterpret_cast<const float4*>(vsrc + (size_t)j * DIM + cc);
        }
        __syncthreads();
        const int jend = (L < base + ACH ? L : base + ACH);
        for (int j = base; j < jend; j++) {
            const float p = ss[i * 132 + j];
            const float4 v0 = *reinterpret_cast<const float4*>(kvs + (j - base) * 68 + g * 8);
            const float4 v1 = *reinterpret_cast<const float4*>(kvs + (j - base) * 68 + g * 8 + 4);
            acc[0] = fmaf(p, v0.x, acc[0]); acc[1] = fmaf(p, v0.y, acc[1]);
            acc[2] = fmaf(p, v0.z, acc[2]); acc[3] = fmaf(p, v0.w, acc[3]);
            acc[4] = fmaf(p, v1.x, acc[4]); acc[5] = fmaf(p, v1.y, acc[5]);
            acc[6] = fmaf(p, v1.z, acc[6]); acc[7] = fmaf(p, v1.w, acc[7]);
        }
    }
    const float inv = rinv[i];
    float* dst = ob + (size_t)(b * NTOK + i) * DIM + h * DH + g * 8;
    *reinterpret_cast<float4*>(dst) =
        make_float4(acc[0] * inv, acc[1] * inv, acc[2] * inv, acc[3] * inv);
    *reinterpret_cast<float4*>(dst + 4) =
        make_float4(acc[4] * inv, acc[5] * inv, acc[6] * inv, acc[7] * inv);
}

// ---------------------------------------------------------------------------
extern "C" void kernel_launch(void* const* d_in, const int* in_sizes, int n_in,
                              void* d_out, int out_size)
{
    const float* x  = (const float*)d_in[0];
    const float* l  = (const float*)d_in[1];
    const float* Wq = (const float*)d_in[2];
    const float* Wk = (const float*)d_in[3];
    const float* Wv = (const float*)d_in[4];
    const float* Wo = (const float*)d_in[5];
    const float* bo = (const float*)d_in[6];
    float* out = (float*)d_out;

    void *pq, *pk, *pv, *pa;
    cudaGetSymbolAddress(&pq, g_q);
    cudaGetSymbolAddress(&pk, g_k);
    cudaGetSymbolAddress(&pv, g_v);
    cudaGetSymbolAddress(&pa, g_ao);
    float* q  = (float*)pq;
    float* k  = (float*)pk;
    float* v  = (float*)pv;
    float* ao = (float*)pa;

    dim3 blk(256);
    gemm_f16<false><<<dim3(4, QROWS / 128), blk>>>(x, Wq, nullptr, q);
    gemm_f16_packed<<<dim3(4, PACKED_TILES), blk>>>(l, Wk, k);
    gemm_f16_packed<<<dim3(4, PACKED_TILES), blk>>>(l, Wv, v);
    attn_kernel<<<NB * NHEADS, 128>>>(q, k, v, ao);
    gemm_f16<true><<<dim3(4, QROWS / 128), blk>>>(ao, Wo, bo, out);
}